// round 5
// baseline (speedup 1.0000x reference)
#include <cuda_runtime.h>

#define BATCH 64
#define SEQ   341
#define DIM   768
#define HEADS 12
#define HD    64
#define MTOT  (BATCH*SEQ)     // 21824
#define QKVC  (3*DIM)         // 2304

// Scratch (allocation-free).
__device__ unsigned g_xp[(size_t)MTOT * DIM];      // x, tf32+permuted
__device__ unsigned g_wqkv[(size_t)QKVC * DIM];    // qkv_w, tf32+permuted
__device__ unsigned g_wproj[(size_t)DIM * DIM];    // proj_w, tf32+permuted
__device__ float    g_qkv[(size_t)MTOT * QKVC];    // qkv activations (tf32-rounded fp32)
__device__ unsigned g_attn[(size_t)MTOT * DIM];    // attn out, tf32+permuted

__device__ __forceinline__ unsigned f2tf(float f) {
    unsigned u;
    asm("cvt.rna.tf32.f32 %0, %1;" : "=r"(u) : "f"(f));
    return u;
}
__device__ __forceinline__ unsigned sptr(const void* p) {
    return (unsigned)__cvta_generic_to_shared(p);
}
__device__ __forceinline__ void mma8(float* d, const unsigned* a, unsigned b0, unsigned b1) {
    asm volatile(
        "mma.sync.aligned.m16n8k8.row.col.f32.tf32.tf32.f32 "
        "{%0,%1,%2,%3}, {%4,%5,%6,%7}, {%8,%9}, {%0,%1,%2,%3};"
        : "+f"(d[0]), "+f"(d[1]), "+f"(d[2]), "+f"(d[3])
        : "r"(a[0]), "r"(a[1]), "r"(a[2]), "r"(a[3]), "r"(b0), "r"(b1));
}

// ---------------------------------------------------------------------------
// prep: tf32-round + permute columns within 16-col groups:
//   p(j) = (j & ~15) | ((j%4)*4 + (j%16)/4)
// ---------------------------------------------------------------------------
__global__ void prep_tf32(const float* __restrict__ in, unsigned* __restrict__ out,
                          int total, int K) {
    int i = blockIdx.x * blockDim.x + threadIdx.x;
    if (i >= total) return;
    int r = i / K, j = i - r * K;
    int pj = (j & ~15) | (((j & 3) << 2) | ((j >> 2) & 3));
    out[(size_t)r * K + pj] = f2tf(in[i]);
}

// ---------------------------------------------------------------------------
// C[M,Nout] = A[M,K] * W[Nout,K]^T + bias, tf32 mma, 3-stage cp.async.
// A, W pre-converted to tf32 bits, columns permuted per 16-group so that one
// LDS.128 delivers a thread's fragments for two k-steps. 128x128x16 tiles,
// 256 threads = 8 warps (4 M x 2 N). Row stride 16 words: conflict-free.
// cvt_out: round outputs to tf32 (for feeding attention).
// ---------------------------------------------------------------------------
#define KT 16
#define SSZ (128 * KT)
__global__ __launch_bounds__(256) void gemm_tf32p(
    const unsigned* __restrict__ A, const unsigned* __restrict__ W,
    const float* __restrict__ bias, float* __restrict__ C,
    int M, int Nout, int K, int cvt_out)
{
    extern __shared__ unsigned smu[];
    unsigned* As = smu;
    unsigned* Ws = smu + 3 * SSZ;

    const int tid = threadIdx.x;
    const int wid = tid >> 5, lane = tid & 31;
    const int g = lane >> 2, c = lane & 3;
    const int wm = (wid & 3) * 32, wn = (wid >> 2) * 64;
    const int m0 = blockIdx.y * 128, n0 = blockIdx.x * 128;

    float acc[2][8][4];
#pragma unroll
    for (int mi = 0; mi < 2; mi++)
#pragma unroll
        for (int nf = 0; nf < 8; nf++)
#pragma unroll
            for (int t = 0; t < 4; t++) acc[mi][nf][t] = 0.f;

    const int niter = K >> 4;

#define ISSUE(it, s)                                                          \
    {                                                                         \
        int _k0 = (it) << 4;                                                  \
        _Pragma("unroll")                                                     \
        for (int p = 0; p < 2; p++) {                                         \
            int ch = tid + p * 256;                                           \
            int row = ch >> 2, col = (ch & 3) << 2;                           \
            int m = m0 + row;                                                 \
            unsigned da = sptr(&As[(s) * SSZ + row * KT + col]);              \
            const unsigned* ga = A + (size_t)(m < M ? m : 0) * K + _k0 + col; \
            int szv = (m < M) ? 16 : 0;                                       \
            asm volatile("cp.async.ca.shared.global [%0],[%1],16,%2;"         \
                         :: "r"(da), "l"(ga), "r"(szv));                      \
            unsigned dw = sptr(&Ws[(s) * SSZ + row * KT + col]);              \
            const unsigned* gw = W + (size_t)(n0 + row) * K + _k0 + col;      \
            asm volatile("cp.async.ca.shared.global [%0],[%1],16;"            \
                         :: "r"(dw), "l"(gw));                                \
        }                                                                     \
    }

    ISSUE(0, 0); asm volatile("cp.async.commit_group;");
    ISSUE(1, 1); asm volatile("cp.async.commit_group;");

    int buf = 0;
    for (int it = 0; it < niter; ++it) {
        asm volatile("cp.async.wait_group 1;");
        __syncthreads();
        if (it + 2 < niter) {
            int s = (buf + 2 >= 3) ? buf - 1 : buf + 2;
            ISSUE(it + 2, s);
        }
        asm volatile("cp.async.commit_group;");

        const unsigned* Ab = As + buf * SSZ;
        const unsigned* Wb = Ws + buf * SSZ;

        uint4 qa[2][2];
#pragma unroll
        for (int mi = 0; mi < 2; mi++) {
            qa[mi][0] = *(const uint4*)&Ab[(wm + mi * 16 + g) * KT + 4 * c];
            qa[mi][1] = *(const uint4*)&Ab[(wm + mi * 16 + g + 8) * KT + 4 * c];
        }
        unsigned a0[2][4], a1[2][4];
#pragma unroll
        for (int mi = 0; mi < 2; mi++) {
            a0[mi][0] = qa[mi][0].x; a0[mi][1] = qa[mi][1].x;
            a0[mi][2] = qa[mi][0].y; a0[mi][3] = qa[mi][1].y;
            a1[mi][0] = qa[mi][0].z; a1[mi][1] = qa[mi][1].z;
            a1[mi][2] = qa[mi][0].w; a1[mi][3] = qa[mi][1].w;
        }
#pragma unroll
        for (int nf = 0; nf < 8; nf++) {
            uint4 bv = *(const uint4*)&Wb[(wn + nf * 8 + g) * KT + 4 * c];
            mma8(acc[0][nf], a0[0], bv.x, bv.y);
            mma8(acc[1][nf], a0[1], bv.x, bv.y);
            mma8(acc[0][nf], a1[0], bv.z, bv.w);
            mma8(acc[1][nf], a1[1], bv.z, bv.w);
        }
        buf = (buf + 1 == 3) ? 0 : buf + 1;
    }

#pragma unroll
    for (int mi = 0; mi < 2; mi++) {
        int row0 = m0 + wm + mi * 16 + g;
        int row1 = row0 + 8;
#pragma unroll
        for (int nf = 0; nf < 8; nf++) {
            int n = n0 + wn + nf * 8 + 2 * c;
            float2 bv = *(const float2*)&bias[n];
            float2 o0 = make_float2(acc[mi][nf][0] + bv.x, acc[mi][nf][1] + bv.y);
            float2 o1 = make_float2(acc[mi][nf][2] + bv.x, acc[mi][nf][3] + bv.y);
            if (cvt_out) {
                o0.x = __uint_as_float(f2tf(o0.x)); o0.y = __uint_as_float(f2tf(o0.y));
                o1.x = __uint_as_float(f2tf(o1.x)); o1.y = __uint_as_float(f2tf(o1.y));
            }
            if (row0 < M) *(float2*)&C[(size_t)row0 * Nout + n] = o0;
            if (row1 < M) *(float2*)&C[(size_t)row1 * Nout + n] = o1;
        }
    }
#undef ISSUE
}

// ---------------------------------------------------------------------------
// Flash attention, tf32 mma, permuted smem (stride 80 words -> LDS.128
// fragment loads, conflict-free). Inputs from g_qkv are tf32-rounded so
// Q/K/V fragments need no cvt; only P (post-exp) is converted.
// Output written to g_attn tf32+permuted (GEMM2's A format).
// Mask: key allowed iff key < limit(q);
//   limit(q) = 341 (q==0 or q>=85), 5 (q<5), 21 (q<21), 85 (q<85).
// ---------------------------------------------------------------------------
#define AST 80
__global__ __launch_bounds__(128) void attn_mma(
    const float* __restrict__ qkv, unsigned* __restrict__ op)
{
    extern __shared__ float sm[];
    float* Qs  = sm;                  // [64][80]
    float* KPs = sm + 64 * AST;       // [64][80] K tile then P
    float* Vt  = sm + 2 * 64 * AST;   // [64][80] V transposed [d][p(k)]

    const int qt = blockIdx.x;
    const int bh = blockIdx.y;
    const int b = bh / HEADS, h = bh - b * HEADS;
    const int tid = threadIdx.x;
    const int wid = tid >> 5, lane = tid & 31;
    const int g = lane >> 2, c = lane & 3;
    const int wq = wid * 16;
    const int q0 = qt * 64;
    const float* base = qkv + (size_t)b * SEQ * QKVC + h * HD;

    // Q tile: scaled by 1/8 (exact), permuted columns
    for (int idx = tid; idx < 1024; idx += 128) {
        int row = idx >> 4, c4 = (idx & 15) << 2;
        int qg = q0 + row;
        float4 v = make_float4(0.f, 0.f, 0.f, 0.f);
        if (qg < SEQ) v = *(const float4*)&base[(size_t)qg * QKVC + c4];
        int cb = (c4 & 48) + ((c4 & 12) >> 2);
        float* d = &Qs[row * AST + cb];
        d[0] = v.x * 0.125f; d[4] = v.y * 0.125f; d[8] = v.z * 0.125f; d[12] = v.w * 0.125f;
    }

    const int row0 = q0 + wq + g;
    const int row1 = row0 + 8;
    const int limit0 = (row0 == 0 || row0 >= 85) ? SEQ : (row0 < 5 ? 5 : (row0 < 21 ? 21 : 85));
    const int limit1 = (row1 == 0 || row1 >= 85) ? SEQ : (row1 < 5 ? 5 : (row1 < 21 ? 21 : 85));

    float m0 = -1e30f, m1 = -1e30f, l0 = 0.f, l1 = 0.f;
    float O[8][4];
#pragma unroll
    for (int nf = 0; nf < 8; nf++)
#pragma unroll
        for (int t = 0; t < 4; t++) O[nf][t] = 0.f;

    for (int kt = 0; kt < 6; kt++) {
        const int k0 = kt * 64;
        __syncthreads();
        for (int idx = tid; idx < 1024; idx += 128) {
            int row = idx >> 4, c4 = (idx & 15) << 2;
            int kg = k0 + row;
            float4 kv = make_float4(0.f, 0.f, 0.f, 0.f);
            float4 vv = make_float4(0.f, 0.f, 0.f, 0.f);
            if (kg < SEQ) {
                kv = *(const float4*)&base[(size_t)kg * QKVC + DIM + c4];
                vv = *(const float4*)&base[(size_t)kg * QKVC + 2 * DIM + c4];
            }
            int cb = (c4 & 48) + ((c4 & 12) >> 2);
            float* kd = &KPs[row * AST + cb];
            kd[0] = kv.x; kd[4] = kv.y; kd[8] = kv.z; kd[12] = kv.w;
            // V transposed: Vt[d][p(k)], k = row
            int pk = (row & 48) | (((row & 3) << 2) | ((row >> 2) & 3));
            Vt[(c4 + 0) * AST + pk] = vv.x;
            Vt[(c4 + 1) * AST + pk] = vv.y;
            Vt[(c4 + 2) * AST + pk] = vv.z;
            Vt[(c4 + 3) * AST + pk] = vv.w;
        }
        __syncthreads();

        // S = Q*K^T
        float S[8][4];
#pragma unroll
        for (int nf = 0; nf < 8; nf++)
#pragma unroll
            for (int t = 0; t < 4; t++) S[nf][t] = 0.f;

#pragma unroll
        for (int grp = 0; grp < 4; grp++) {
            const int kb = grp * 16 + 4 * c;
            uint4 qg4  = *(const uint4*)&Qs[(wq + g) * AST + kb];
            uint4 qg8  = *(const uint4*)&Qs[(wq + g + 8) * AST + kb];
            unsigned a0[4] = {qg4.x, qg8.x, qg4.y, qg8.y};
            unsigned a1[4] = {qg4.z, qg8.z, qg4.w, qg8.w};
#pragma unroll
            for (int nf = 0; nf < 8; nf++) {
                uint4 bv = *(const uint4*)&KPs[(nf * 8 + g) * AST + kb];
                mma8(S[nf], a0, bv.x, bv.y);
                mma8(S[nf], a1, bv.z, bv.w);
            }
        }

        // mask + row max
        float mx0 = -1e30f, mx1 = -1e30f;
#pragma unroll
        for (int nf = 0; nf < 8; nf++) {
            int key0 = k0 + nf * 8 + 2 * c;
            int key1 = key0 + 1;
            S[nf][0] = (key0 < limit0) ? S[nf][0] : -1e30f;
            S[nf][1] = (key1 < limit0) ? S[nf][1] : -1e30f;
            S[nf][2] = (key0 < limit1) ? S[nf][2] : -1e30f;
            S[nf][3] = (key1 < limit1) ? S[nf][3] : -1e30f;
            mx0 = fmaxf(mx0, fmaxf(S[nf][0], S[nf][1]));
            mx1 = fmaxf(mx1, fmaxf(S[nf][2], S[nf][3]));
        }
        mx0 = fmaxf(mx0, __shfl_xor_sync(0xffffffffu, mx0, 1));
        mx0 = fmaxf(mx0, __shfl_xor_sync(0xffffffffu, mx0, 2));
        mx1 = fmaxf(mx1, __shfl_xor_sync(0xffffffffu, mx1, 1));
        mx1 = fmaxf(mx1, __shfl_xor_sync(0xffffffffu, mx1, 2));

        float mn0 = fmaxf(m0, mx0), mn1 = fmaxf(m1, mx1);
        float al0 = __expf(m0 - mn0), al1 = __expf(m1 - mn1);
        m0 = mn0; m1 = mn1;

        float r0 = 0.f, r1 = 0.f;
#pragma unroll
        for (int nf = 0; nf < 8; nf++) {
            S[nf][0] = __expf(S[nf][0] - mn0);
            S[nf][1] = __expf(S[nf][1] - mn0);
            S[nf][2] = __expf(S[nf][2] - mn1);
            S[nf][3] = __expf(S[nf][3] - mn1);
            r0 += S[nf][0] + S[nf][1];
            r1 += S[nf][2] + S[nf][3];
        }
        r0 += __shfl_xor_sync(0xffffffffu, r0, 1);
        r0 += __shfl_xor_sync(0xffffffffu, r0, 2);
        r1 += __shfl_xor_sync(0xffffffffu, r1, 1);
        r1 += __shfl_xor_sync(0xffffffffu, r1, 2);
        l0 = l0 * al0 + r0;
        l1 = l1 * al1 + r1;
#pragma unroll
        for (int nf = 0; nf < 8; nf++) {
            O[nf][0] *= al0; O[nf][1] *= al0;
            O[nf][2] *= al1; O[nf][3] *= al1;
        }

        // P -> smem (permuted cols), warp-local rows
        __syncthreads();
#pragma unroll
        for (int nf = 0; nf < 8; nf++) {
            int d0 = nf * 8 + 2 * c;
            int pd = (d0 & ~15) | (((d0 & 3) << 2) | ((d0 >> 2) & 3));
            KPs[(wq + g) * AST + pd]     = S[nf][0];
            KPs[(wq + g) * AST + pd + 4] = S[nf][1];
            KPs[(wq + g + 8) * AST + pd]     = S[nf][2];
            KPs[(wq + g + 8) * AST + pd + 4] = S[nf][3];
        }
        __syncwarp();

        // O += P @ V
#pragma unroll
        for (int grp = 0; grp < 4; grp++) {
            const int kb = grp * 16 + 4 * c;
            uint4 pg  = *(const uint4*)&KPs[(wq + g) * AST + kb];
            uint4 pg8 = *(const uint4*)&KPs[(wq + g + 8) * AST + kb];
            unsigned a0[4] = {f2tf(__uint_as_float(pg.x)), f2tf(__uint_as_float(pg8.x)),
                              f2tf(__uint_as_float(pg.y)), f2tf(__uint_as_float(pg8.y))};
            unsigned a1[4] = {f2tf(__uint_as_float(pg.z)), f2tf(__uint_as_float(pg8.z)),
                              f2tf(__uint_as_float(pg.w)), f2tf(__uint_as_float(pg8.w))};
#pragma unroll
            for (int nf = 0; nf < 8; nf++) {
                uint4 vv = *(const uint4*)&Vt[(nf * 8 + g) * AST + kb];
                mma8(O[nf], a0, vv.x, vv.y);
                mma8(O[nf], a1, vv.z, vv.w);
            }
        }
    }

    // normalize + store tf32+permuted to g_attn [b, n, h*64 + p(d)]
    float inv0 = 1.f / l0, inv1 = 1.f / l1;
#pragma unroll
    for (int nf = 0; nf < 8; nf++) {
        int d0 = nf * 8 + 2 * c;
        int pd = (d0 & ~15) | (((d0 & 3) << 2) | ((d0 >> 2) & 3));
        int col = h * HD + pd;
        if (row0 < SEQ) {
            unsigned* o = &op[(size_t)(b * SEQ + row0) * DIM + col];
            o[0] = f2tf(O[nf][0] * inv0);
            o[4] = f2tf(O[nf][1] * inv0);
        }
        if (row1 < SEQ) {
            unsigned* o = &op[(size_t)(b * SEQ + row1) * DIM + col];
            o[0] = f2tf(O[nf][2] * inv1);
            o[4] = f2tf(O[nf][3] * inv1);
        }
    }
}

extern "C" void kernel_launch(void* const* d_in, const int* in_sizes, int n_in,
                              void* d_out, int out_size) {
    const float* x      = (const float*)d_in[0];
    const float* qkv_w  = (const float*)d_in[1];
    const float* qkv_b  = (const float*)d_in[2];
    const float* proj_w = (const float*)d_in[3];
    const float* proj_b = (const float*)d_in[4];
    float* out = (float*)d_out;

    unsigned *xp, *wqkvp, *wprojp, *attnp;
    float* qkvp;
    cudaGetSymbolAddress((void**)&xp, g_xp);
    cudaGetSymbolAddress((void**)&wqkvp, g_wqkv);
    cudaGetSymbolAddress((void**)&wprojp, g_wproj);
    cudaGetSymbolAddress((void**)&qkvp, g_qkv);
    cudaGetSymbolAddress((void**)&attnp, g_attn);

    const int gemm_smem = 6 * SSZ * 4;            // 49152
    const int attn_smem = 3 * 64 * AST * 4;       // 61440
    cudaFuncSetAttribute(gemm_tf32p, cudaFuncAttributeMaxDynamicSharedMemorySize, gemm_smem);
    cudaFuncSetAttribute(attn_mma, cudaFuncAttributeMaxDynamicSharedMemorySize, attn_smem);

    prep_tf32<<<(MTOT * DIM + 255) / 256, 256>>>(x, xp, MTOT * DIM, DIM);
    prep_tf32<<<(QKVC * DIM + 255) / 256, 256>>>(qkv_w, wqkvp, QKVC * DIM, DIM);
    prep_tf32<<<(DIM * DIM + 255) / 256, 256>>>(proj_w, wprojp, DIM * DIM, DIM);

    dim3 g1(QKVC / 128, (MTOT + 127) / 128);
    gemm_tf32p<<<g1, 256, gemm_smem>>>(xp, wqkvp, qkv_b, qkvp, MTOT, QKVC, DIM, 1);

    dim3 g2(6, BATCH * HEADS);
    attn_mma<<<g2, 128, attn_smem>>>(qkvp, attnp);

    dim3 g3(DIM / 128, (MTOT + 127) / 128);
    gemm_tf32p<<<g3, 256, gemm_smem>>>(attnp, wprojp, proj_b, out, MTOT, DIM, DIM, 0);
}

// round 6
// speedup vs baseline: 1.1489x; 1.1489x over previous
#include <cuda_runtime.h>

#define BATCH 64
#define SEQ   341
#define DIM   768
#define HEADS 12
#define HD    64
#define MTOT  (BATCH*SEQ)     // 21824
#define QKVC  (3*DIM)         // 2304

// Scratch (allocation-free).
__device__ unsigned g_xp[(size_t)MTOT * DIM];      // x, tf32+permuted
__device__ unsigned g_wqkv[(size_t)QKVC * DIM];    // qkv_w, tf32+permuted
__device__ unsigned g_wproj[(size_t)DIM * DIM];    // proj_w, tf32+permuted
__device__ float    g_qkv[(size_t)MTOT * QKVC];    // qkv activations (tf32-rounded fp32)
__device__ unsigned g_attn[(size_t)MTOT * DIM];    // attn out, tf32+permuted

__device__ __forceinline__ unsigned f2tf(float f) {
    unsigned u;
    asm("cvt.rna.tf32.f32 %0, %1;" : "=r"(u) : "f"(f));
    return u;
}
__device__ __forceinline__ unsigned sptr(const void* p) {
    return (unsigned)__cvta_generic_to_shared(p);
}
__device__ __forceinline__ void mma8(float* d, const unsigned* a, unsigned b0, unsigned b1) {
    asm volatile(
        "mma.sync.aligned.m16n8k8.row.col.f32.tf32.tf32.f32 "
        "{%0,%1,%2,%3}, {%4,%5,%6,%7}, {%8,%9}, {%0,%1,%2,%3};"
        : "+f"(d[0]), "+f"(d[1]), "+f"(d[2]), "+f"(d[3])
        : "r"(a[0]), "r"(a[1]), "r"(a[2]), "r"(a[3]), "r"(b0), "r"(b1));
}

// ---------------------------------------------------------------------------
// prep: tf32-round + permute columns within 16-col groups:
//   p(j) = (j & ~15) | ((j%4)*4 + (j%16)/4)
// ---------------------------------------------------------------------------
__global__ void prep_tf32(const float* __restrict__ in, unsigned* __restrict__ out,
                          int total, int K) {
    int i = blockIdx.x * blockDim.x + threadIdx.x;
    if (i >= total) return;
    int r = i / K, j = i - r * K;
    int pj = (j & ~15) | (((j & 3) << 2) | ((j >> 2) & 3));
    out[(size_t)r * K + pj] = f2tf(in[i]);
}

// ---------------------------------------------------------------------------
// C[M,Nout] = A[M,K] * W[Nout,K]^T + bias, tf32 mma, 2-stage cp.async,
// 128x128x32 tiles, 256 threads = 8 warps (4 M x 2 N). Operands pre-converted
// to tf32 bits with columns permuted per 16-group: one LDS.128 = fragments
// for two k-steps. Physical row stride 48 words (== 16 mod 32: the two
// g-parities inside each 8-lane LDS.128 phase are 16 banks apart ->
// conflict-free). launch_bounds(256,2) pins 2 CTAs/SM.
// ---------------------------------------------------------------------------
#define KT   32
#define KTP  48
#define SSZ  (128 * KTP)
__global__ __launch_bounds__(256, 2) void gemm_tf32p(
    const unsigned* __restrict__ A, const unsigned* __restrict__ W,
    const float* __restrict__ bias, float* __restrict__ C,
    int M, int Nout, int K, int cvt_out)
{
    extern __shared__ unsigned smu[];
    unsigned* As = smu;             // 2 stages
    unsigned* Ws = smu + 2 * SSZ;   // 2 stages

    const int tid = threadIdx.x;
    const int wid = tid >> 5, lane = tid & 31;
    const int g = lane >> 2, c = lane & 3;
    const int wm = (wid & 3) * 32, wn = (wid >> 2) * 64;
    const int m0 = blockIdx.y * 128, n0 = blockIdx.x * 128;

    float acc[2][8][4];
#pragma unroll
    for (int mi = 0; mi < 2; mi++)
#pragma unroll
        for (int nf = 0; nf < 8; nf++)
#pragma unroll
            for (int t = 0; t < 4; t++) acc[mi][nf][t] = 0.f;

    const int niter = K >> 5;

#define ISSUE(it, s)                                                          \
    {                                                                         \
        int _k0 = (it) << 5;                                                  \
        _Pragma("unroll")                                                     \
        for (int p = 0; p < 4; p++) {                                         \
            int ch = tid + p * 256;                                           \
            int row = ch >> 3, col = (ch & 7) << 2;                           \
            int m = m0 + row;                                                 \
            unsigned da = sptr(&As[(s) * SSZ + row * KTP + col]);             \
            const unsigned* ga = A + (size_t)(m < M ? m : 0) * K + _k0 + col; \
            int szv = (m < M) ? 16 : 0;                                       \
            asm volatile("cp.async.ca.shared.global [%0],[%1],16,%2;"         \
                         :: "r"(da), "l"(ga), "r"(szv));                      \
            unsigned dw = sptr(&Ws[(s) * SSZ + row * KTP + col]);             \
            const unsigned* gw = W + (size_t)(n0 + row) * K + _k0 + col;      \
            asm volatile("cp.async.ca.shared.global [%0],[%1],16;"            \
                         :: "r"(dw), "l"(gw));                                \
        }                                                                     \
    }

    ISSUE(0, 0); asm volatile("cp.async.commit_group;");

    int buf = 0;
    for (int it = 0; it < niter; ++it) {
        __syncthreads();               // all warps done reading stage buf^1
        if (it + 1 < niter) {
            ISSUE(it + 1, buf ^ 1);
            asm volatile("cp.async.commit_group;");
            asm volatile("cp.async.wait_group 1;");
        } else {
            asm volatile("cp.async.wait_group 0;");
        }
        __syncthreads();               // stage buf visible to all

        const unsigned* Ab = As + buf * SSZ;
        const unsigned* Wb = Ws + buf * SSZ;

#pragma unroll
        for (int grp = 0; grp < 2; grp++) {
            const int gb = grp * 16 + 4 * c;
            uint4 qa0[2], qa1[2];
#pragma unroll
            for (int mi = 0; mi < 2; mi++) {
                qa0[mi] = *(const uint4*)&Ab[(wm + mi * 16 + g) * KTP + gb];
                qa1[mi] = *(const uint4*)&Ab[(wm + mi * 16 + g + 8) * KTP + gb];
            }
            unsigned a0[2][4], a1[2][4];
#pragma unroll
            for (int mi = 0; mi < 2; mi++) {
                a0[mi][0] = qa0[mi].x; a0[mi][1] = qa1[mi].x;
                a0[mi][2] = qa0[mi].y; a0[mi][3] = qa1[mi].y;
                a1[mi][0] = qa0[mi].z; a1[mi][1] = qa1[mi].z;
                a1[mi][2] = qa0[mi].w; a1[mi][3] = qa1[mi].w;
            }
#pragma unroll
            for (int nf = 0; nf < 8; nf++) {
                uint4 bv = *(const uint4*)&Wb[(wn + nf * 8 + g) * KTP + gb];
                mma8(acc[0][nf], a0[0], bv.x, bv.y);
                mma8(acc[1][nf], a0[1], bv.x, bv.y);
                mma8(acc[0][nf], a1[0], bv.z, bv.w);
                mma8(acc[1][nf], a1[1], bv.z, bv.w);
            }
        }
        buf ^= 1;
    }

#pragma unroll
    for (int mi = 0; mi < 2; mi++) {
        int row0 = m0 + wm + mi * 16 + g;
        int row1 = row0 + 8;
#pragma unroll
        for (int nf = 0; nf < 8; nf++) {
            int n = n0 + wn + nf * 8 + 2 * c;
            float2 bv = *(const float2*)&bias[n];
            float2 o0 = make_float2(acc[mi][nf][0] + bv.x, acc[mi][nf][1] + bv.y);
            float2 o1 = make_float2(acc[mi][nf][2] + bv.x, acc[mi][nf][3] + bv.y);
            if (cvt_out) {
                o0.x = __uint_as_float(f2tf(o0.x)); o0.y = __uint_as_float(f2tf(o0.y));
                o1.x = __uint_as_float(f2tf(o1.x)); o1.y = __uint_as_float(f2tf(o1.y));
            }
            if (row0 < M) *(float2*)&C[(size_t)row0 * Nout + n] = o0;
            if (row1 < M) *(float2*)&C[(size_t)row1 * Nout + n] = o1;
        }
    }
#undef ISSUE
}

// ---------------------------------------------------------------------------
// Flash attention, tf32 mma. Q/K/P in permuted smem (stride 80 -> LDS.128
// fragment loads, conflict-free). V row-major stride 72 (conflict-free
// float4 stores; scalar fragment loads are bank-bijective). Inputs are
// tf32-rounded so Q/K/V use raw bits; only P (post-exp) is converted.
// Output: g_attn tf32+permuted (GEMM2's A format).
// Mask: key allowed iff key < limit(q);
//   limit(q) = 341 (q==0 or q>=85), 5 (q<5), 21 (q<21), 85 (q<85).
// ---------------------------------------------------------------------------
#define AST 80
#define VST 72
__global__ __launch_bounds__(128) void attn_mma(
    const float* __restrict__ qkv, unsigned* __restrict__ op)
{
    extern __shared__ float sm[];
    float* Qs  = sm;                  // [64][80] permuted cols
    float* KPs = sm + 64 * AST;       // [64][80] K tile (permuted), then P
    float* Vs  = sm + 2 * 64 * AST;   // [64][72] row-major [k][d]

    const int qt = blockIdx.x;
    const int bh = blockIdx.y;
    const int b = bh / HEADS, h = bh - b * HEADS;
    const int tid = threadIdx.x;
    const int wid = tid >> 5, lane = tid & 31;
    const int g = lane >> 2, c = lane & 3;
    const int wq = wid * 16;
    const int q0 = qt * 64;
    const float* base = qkv + (size_t)b * SEQ * QKVC + h * HD;

    // Q tile: scaled by 1/8 (exact in tf32), permuted columns
    for (int idx = tid; idx < 1024; idx += 128) {
        int row = idx >> 4, c4 = (idx & 15) << 2;
        int qg = q0 + row;
        float4 v = make_float4(0.f, 0.f, 0.f, 0.f);
        if (qg < SEQ) v = *(const float4*)&base[(size_t)qg * QKVC + c4];
        int cb = (c4 & 48) + ((c4 & 12) >> 2);
        float* d = &Qs[row * AST + cb];
        d[0] = v.x * 0.125f; d[4] = v.y * 0.125f; d[8] = v.z * 0.125f; d[12] = v.w * 0.125f;
    }

    const int row0 = q0 + wq + g;
    const int row1 = row0 + 8;
    const int limit0 = (row0 == 0 || row0 >= 85) ? SEQ : (row0 < 5 ? 5 : (row0 < 21 ? 21 : 85));
    const int limit1 = (row1 == 0 || row1 >= 85) ? SEQ : (row1 < 5 ? 5 : (row1 < 21 ? 21 : 85));

    float m0 = -1e30f, m1 = -1e30f, l0 = 0.f, l1 = 0.f;
    float O[8][4];
#pragma unroll
    for (int nf = 0; nf < 8; nf++)
#pragma unroll
        for (int t = 0; t < 4; t++) O[nf][t] = 0.f;

    for (int kt = 0; kt < 6; kt++) {
        const int k0 = kt * 64;
        __syncthreads();
        for (int idx = tid; idx < 1024; idx += 128) {
            int row = idx >> 4, c4 = (idx & 15) << 2;
            int kg = k0 + row;
            float4 kv = make_float4(0.f, 0.f, 0.f, 0.f);
            float4 vv = make_float4(0.f, 0.f, 0.f, 0.f);
            if (kg < SEQ) {
                kv = *(const float4*)&base[(size_t)kg * QKVC + DIM + c4];
                vv = *(const float4*)&base[(size_t)kg * QKVC + 2 * DIM + c4];
            }
            int cb = (c4 & 48) + ((c4 & 12) >> 2);
            float* kd = &KPs[row * AST + cb];
            kd[0] = kv.x; kd[4] = kv.y; kd[8] = kv.z; kd[12] = kv.w;
            *(float4*)&Vs[row * VST + c4] = vv;      // row-major, conflict-free
        }
        __syncthreads();

        // S = Q*K^T
        float S[8][4];
#pragma unroll
        for (int nf = 0; nf < 8; nf++)
#pragma unroll
            for (int t = 0; t < 4; t++) S[nf][t] = 0.f;

#pragma unroll
        for (int grp = 0; grp < 4; grp++) {
            const int kb = grp * 16 + 4 * c;
            uint4 qg4  = *(const uint4*)&Qs[(wq + g) * AST + kb];
            uint4 qg8  = *(const uint4*)&Qs[(wq + g + 8) * AST + kb];
            unsigned a0[4] = {qg4.x, qg8.x, qg4.y, qg8.y};
            unsigned a1[4] = {qg4.z, qg8.z, qg4.w, qg8.w};
#pragma unroll
            for (int nf = 0; nf < 8; nf++) {
                uint4 bv = *(const uint4*)&KPs[(nf * 8 + g) * AST + kb];
                mma8(S[nf], a0, bv.x, bv.y);
                mma8(S[nf], a1, bv.z, bv.w);
            }
        }

        // mask + row max
        float mx0 = -1e30f, mx1 = -1e30f;
#pragma unroll
        for (int nf = 0; nf < 8; nf++) {
            int key0 = k0 + nf * 8 + 2 * c;
            int key1 = key0 + 1;
            S[nf][0] = (key0 < limit0) ? S[nf][0] : -1e30f;
            S[nf][1] = (key1 < limit0) ? S[nf][1] : -1e30f;
            S[nf][2] = (key0 < limit1) ? S[nf][2] : -1e30f;
            S[nf][3] = (key1 < limit1) ? S[nf][3] : -1e30f;
            mx0 = fmaxf(mx0, fmaxf(S[nf][0], S[nf][1]));
            mx1 = fmaxf(mx1, fmaxf(S[nf][2], S[nf][3]));
        }
        mx0 = fmaxf(mx0, __shfl_xor_sync(0xffffffffu, mx0, 1));
        mx0 = fmaxf(mx0, __shfl_xor_sync(0xffffffffu, mx0, 2));
        mx1 = fmaxf(mx1, __shfl_xor_sync(0xffffffffu, mx1, 1));
        mx1 = fmaxf(mx1, __shfl_xor_sync(0xffffffffu, mx1, 2));

        float mn0 = fmaxf(m0, mx0), mn1 = fmaxf(m1, mx1);
        float al0 = __expf(m0 - mn0), al1 = __expf(m1 - mn1);
        m0 = mn0; m1 = mn1;

        float r0 = 0.f, r1 = 0.f;
#pragma unroll
        for (int nf = 0; nf < 8; nf++) {
            S[nf][0] = __expf(S[nf][0] - mn0);
            S[nf][1] = __expf(S[nf][1] - mn0);
            S[nf][2] = __expf(S[nf][2] - mn1);
            S[nf][3] = __expf(S[nf][3] - mn1);
            r0 += S[nf][0] + S[nf][1];
            r1 += S[nf][2] + S[nf][3];
        }
        r0 += __shfl_xor_sync(0xffffffffu, r0, 1);
        r0 += __shfl_xor_sync(0xffffffffu, r0, 2);
        r1 += __shfl_xor_sync(0xffffffffu, r1, 1);
        r1 += __shfl_xor_sync(0xffffffffu, r1, 2);
        l0 = l0 * al0 + r0;
        l1 = l1 * al1 + r1;
#pragma unroll
        for (int nf = 0; nf < 8; nf++) {
            O[nf][0] *= al0; O[nf][1] *= al0;
            O[nf][2] *= al1; O[nf][3] *= al1;
        }

        // P -> smem (permuted cols), warp-local rows
        __syncthreads();
#pragma unroll
        for (int nf = 0; nf < 8; nf++) {
            int d0 = nf * 8 + 2 * c;
            int pd = (d0 & ~15) | (((d0 & 3) << 2) | ((d0 >> 2) & 3));
            KPs[(wq + g) * AST + pd]     = S[nf][0];
            KPs[(wq + g) * AST + pd + 4] = S[nf][1];
            KPs[(wq + g + 8) * AST + pd]     = S[nf][2];
            KPs[(wq + g + 8) * AST + pd + 4] = S[nf][3];
        }
        __syncwarp();

        // O += P @ V  (P via permuted uint4 + cvt; V raw bits, scalar loads)
#pragma unroll
        for (int grp = 0; grp < 4; grp++) {
            const int kb = grp * 16 + 4 * c;
            const int kr = grp * 16 + c;
            uint4 pg  = *(const uint4*)&KPs[(wq + g) * AST + kb];
            uint4 pg8 = *(const uint4*)&KPs[(wq + g + 8) * AST + kb];
            unsigned a0[4] = {f2tf(__uint_as_float(pg.x)), f2tf(__uint_as_float(pg8.x)),
                              f2tf(__uint_as_float(pg.y)), f2tf(__uint_as_float(pg8.y))};
            unsigned a1[4] = {f2tf(__uint_as_float(pg.z)), f2tf(__uint_as_float(pg8.z)),
                              f2tf(__uint_as_float(pg.w)), f2tf(__uint_as_float(pg8.w))};
#pragma unroll
            for (int nf = 0; nf < 8; nf++) {
                const int dcol = nf * 8 + g;
                unsigned b0a = __float_as_uint(Vs[(kr)      * VST + dcol]);
                unsigned b1a = __float_as_uint(Vs[(kr + 4)  * VST + dcol]);
                unsigned b0b = __float_as_uint(Vs[(kr + 8)  * VST + dcol]);
                unsigned b1b = __float_as_uint(Vs[(kr + 12) * VST + dcol]);
                mma8(O[nf], a0, b0a, b1a);
                mma8(O[nf], a1, b0b, b1b);
            }
        }
    }

    // normalize + store tf32+permuted to g_attn [b, n, h*64 + p(d)]
    float inv0 = 1.f / l0, inv1 = 1.f / l1;
#pragma unroll
    for (int nf = 0; nf < 8; nf++) {
        int d0 = nf * 8 + 2 * c;
        int pd = (d0 & ~15) | (((d0 & 3) << 2) | ((d0 >> 2) & 3));
        int col = h * HD + pd;
        if (row0 < SEQ) {
            unsigned* o = &op[(size_t)(b * SEQ + row0) * DIM + col];
            o[0] = f2tf(O[nf][0] * inv0);
            o[4] = f2tf(O[nf][1] * inv0);
        }
        if (row1 < SEQ) {
            unsigned* o = &op[(size_t)(b * SEQ + row1) * DIM + col];
            o[0] = f2tf(O[nf][2] * inv1);
            o[4] = f2tf(O[nf][3] * inv1);
        }
    }
}

extern "C" void kernel_launch(void* const* d_in, const int* in_sizes, int n_in,
                              void* d_out, int out_size) {
    const float* x      = (const float*)d_in[0];
    const float* qkv_w  = (const float*)d_in[1];
    const float* qkv_b  = (const float*)d_in[2];
    const float* proj_w = (const float*)d_in[3];
    const float* proj_b = (const float*)d_in[4];
    float* out = (float*)d_out;

    unsigned *xp, *wqkvp, *wprojp, *attnp;
    float* qkvp;
    cudaGetSymbolAddress((void**)&xp, g_xp);
    cudaGetSymbolAddress((void**)&wqkvp, g_wqkv);
    cudaGetSymbolAddress((void**)&wprojp, g_wproj);
    cudaGetSymbolAddress((void**)&qkvp, g_qkv);
    cudaGetSymbolAddress((void**)&attnp, g_attn);

    const int gemm_smem = 4 * SSZ * 4;                       // 98304
    const int attn_smem = (2 * 64 * AST + 64 * VST) * 4;     // 59392
    cudaFuncSetAttribute(gemm_tf32p, cudaFuncAttributeMaxDynamicSharedMemorySize, gemm_smem);
    cudaFuncSetAttribute(attn_mma, cudaFuncAttributeMaxDynamicSharedMemorySize, attn_smem);

    prep_tf32<<<(MTOT * DIM + 255) / 256, 256>>>(x, xp, MTOT * DIM, DIM);
    prep_tf32<<<(QKVC * DIM + 255) / 256, 256>>>(qkv_w, wqkvp, QKVC * DIM, DIM);
    prep_tf32<<<(DIM * DIM + 255) / 256, 256>>>(proj_w, wprojp, DIM * DIM, DIM);

    dim3 g1(QKVC / 128, (MTOT + 127) / 128);
    gemm_tf32p<<<g1, 256, gemm_smem>>>(xp, wqkvp, qkv_b, qkvp, MTOT, QKVC, DIM, 1);

    dim3 g2(6, BATCH * HEADS);
    attn_mma<<<g2, 128, attn_smem>>>(qkvp, attnp);

    dim3 g3(DIM / 128, (MTOT + 127) / 128);
    gemm_tf32p<<<g3, 256, gemm_smem>>>(attnp, wprojp, proj_b, out, MTOT, DIM, DIM, 0);
}

// round 7
// speedup vs baseline: 1.3098x; 1.1400x over previous
#include <cuda_runtime.h>

#define BATCH 64
#define SEQ   341
#define DIM   768
#define HEADS 12
#define HD    64
#define MTOT  (BATCH*SEQ)     // 21824
#define QKVC  (3*DIM)         // 2304

// Scratch (allocation-free).
__device__ unsigned g_xp[(size_t)MTOT * DIM];      // x, tf32+permuted
__device__ unsigned g_wqkv[(size_t)QKVC * DIM];    // qkv_w, tf32+permuted
__device__ unsigned g_wproj[(size_t)DIM * DIM];    // proj_w, tf32+permuted
__device__ float    g_qkv[(size_t)MTOT * QKVC];    // qkv acts; Q,K cols permuted, V plain (all tf32-rounded)
__device__ unsigned g_attn[(size_t)MTOT * DIM];    // attn out, tf32+permuted

__device__ __forceinline__ unsigned f2tf(float f) {
    unsigned u;
    asm("cvt.rna.tf32.f32 %0, %1;" : "=r"(u) : "f"(f));
    return u;
}
__device__ __forceinline__ unsigned sptr(const void* p) {
    return (unsigned)__cvta_generic_to_shared(p);
}
__device__ __forceinline__ void mma8(float* d, const unsigned* a, unsigned b0, unsigned b1) {
    asm volatile(
        "mma.sync.aligned.m16n8k8.row.col.f32.tf32.tf32.f32 "
        "{%0,%1,%2,%3}, {%4,%5,%6,%7}, {%8,%9}, {%0,%1,%2,%3};"
        : "+f"(d[0]), "+f"(d[1]), "+f"(d[2]), "+f"(d[3])
        : "r"(a[0]), "r"(a[1]), "r"(a[2]), "r"(a[3]), "r"(b0), "r"(b1));
}

// ---------------------------------------------------------------------------
// prep: tf32-round + permute columns within 16-col groups (involution):
//   p(j) = (j & ~15) | ((j%4)*4 + (j%16)/4)
// ---------------------------------------------------------------------------
__global__ void prep_tf32(const float* __restrict__ in, unsigned* __restrict__ out,
                          int total, int K) {
    int i = blockIdx.x * blockDim.x + threadIdx.x;
    if (i >= total) return;
    int r = i / K, j = i - r * K;
    int pj = (j & ~15) | (((j & 3) << 2) | ((j >> 2) & 3));
    out[(size_t)r * K + pj] = f2tf(in[i]);
}

// ---------------------------------------------------------------------------
// C[M,Nout] = A[M,K] * W[Nout,K]^T + bias, tf32 mma, 2-stage cp.async,
// 128x128x32 tiles, 256 threads = 8 warps (4 M x 2 N). Operands pre-converted
// to tf32 bits, columns permuted per 16-group: one LDS.128 = fragments for
// two k-steps. Row stride 48 words (==16 mod 32 -> conflict-free LDS.128).
// cvt_out=1 (gemm1): outputs tf32-rounded; Q/K column ranges written in the
// permuted layout (so attention can cp.async them straight into smem),
// V range plain.
// ---------------------------------------------------------------------------
#define KT   32
#define KTP  48
#define SSZ  (128 * KTP)
__global__ __launch_bounds__(256, 2) void gemm_tf32p(
    const unsigned* __restrict__ A, const unsigned* __restrict__ W,
    const float* __restrict__ bias, float* __restrict__ C,
    int M, int Nout, int K, int cvt_out)
{
    extern __shared__ unsigned smu[];
    unsigned* As = smu;             // 2 stages
    unsigned* Ws = smu + 2 * SSZ;   // 2 stages

    const int tid = threadIdx.x;
    const int wid = tid >> 5, lane = tid & 31;
    const int g = lane >> 2, c = lane & 3;
    const int wm = (wid & 3) * 32, wn = (wid >> 2) * 64;
    const int m0 = blockIdx.y * 128, n0 = blockIdx.x * 128;

    float acc[2][8][4];
#pragma unroll
    for (int mi = 0; mi < 2; mi++)
#pragma unroll
        for (int nf = 0; nf < 8; nf++)
#pragma unroll
            for (int t = 0; t < 4; t++) acc[mi][nf][t] = 0.f;

    const int niter = K >> 5;

#define ISSUE(it, s)                                                          \
    {                                                                         \
        int _k0 = (it) << 5;                                                  \
        _Pragma("unroll")                                                     \
        for (int p = 0; p < 4; p++) {                                         \
            int ch = tid + p * 256;                                           \
            int row = ch >> 3, col = (ch & 7) << 2;                           \
            int m = m0 + row;                                                 \
            unsigned da = sptr(&As[(s) * SSZ + row * KTP + col]);             \
            const unsigned* ga = A + (size_t)(m < M ? m : 0) * K + _k0 + col; \
            int szv = (m < M) ? 16 : 0;                                       \
            asm volatile("cp.async.cg.shared.global [%0],[%1],16,%2;"         \
                         :: "r"(da), "l"(ga), "r"(szv));                      \
            unsigned dw = sptr(&Ws[(s) * SSZ + row * KTP + col]);             \
            const unsigned* gw = W + (size_t)(n0 + row) * K + _k0 + col;      \
            asm volatile("cp.async.cg.shared.global [%0],[%1],16;"            \
                         :: "r"(dw), "l"(gw));                                \
        }                                                                     \
    }

    ISSUE(0, 0); asm volatile("cp.async.commit_group;");

    int buf = 0;
    for (int it = 0; it < niter; ++it) {
        __syncthreads();               // all warps done reading stage buf^1
        if (it + 1 < niter) {
            ISSUE(it + 1, buf ^ 1);
            asm volatile("cp.async.commit_group;");
            asm volatile("cp.async.wait_group 1;");
        } else {
            asm volatile("cp.async.wait_group 0;");
        }
        __syncthreads();               // stage buf visible to all

        const unsigned* Ab = As + buf * SSZ;
        const unsigned* Wb = Ws + buf * SSZ;

#pragma unroll
        for (int grp = 0; grp < 2; grp++) {
            const int gb = grp * 16 + 4 * c;
            uint4 qa0[2], qa1[2];
#pragma unroll
            for (int mi = 0; mi < 2; mi++) {
                qa0[mi] = *(const uint4*)&Ab[(wm + mi * 16 + g) * KTP + gb];
                qa1[mi] = *(const uint4*)&Ab[(wm + mi * 16 + g + 8) * KTP + gb];
            }
            unsigned a0[2][4], a1[2][4];
#pragma unroll
            for (int mi = 0; mi < 2; mi++) {
                a0[mi][0] = qa0[mi].x; a0[mi][1] = qa1[mi].x;
                a0[mi][2] = qa0[mi].y; a0[mi][3] = qa1[mi].y;
                a1[mi][0] = qa0[mi].z; a1[mi][1] = qa1[mi].z;
                a1[mi][2] = qa0[mi].w; a1[mi][3] = qa1[mi].w;
            }
#pragma unroll
            for (int nf = 0; nf < 8; nf++) {
                uint4 bv = *(const uint4*)&Wb[(wn + nf * 8 + g) * KTP + gb];
                mma8(acc[0][nf], a0[0], bv.x, bv.y);
                mma8(acc[1][nf], a0[1], bv.x, bv.y);
                mma8(acc[0][nf], a1[0], bv.z, bv.w);
                mma8(acc[1][nf], a1[1], bv.z, bv.w);
            }
        }
        buf ^= 1;
    }

#pragma unroll
    for (int mi = 0; mi < 2; mi++) {
        int row0 = m0 + wm + mi * 16 + g;
        int row1 = row0 + 8;
#pragma unroll
        for (int nf = 0; nf < 8; nf++) {
            int n = n0 + wn + nf * 8 + 2 * c;
            float2 bv = *(const float2*)&bias[n];
            float2 o0 = make_float2(acc[mi][nf][0] + bv.x, acc[mi][nf][1] + bv.y);
            float2 o1 = make_float2(acc[mi][nf][2] + bv.x, acc[mi][nf][3] + bv.y);
            if (cvt_out) {
                float f00 = __uint_as_float(f2tf(o0.x)), f01 = __uint_as_float(f2tf(o0.y));
                float f10 = __uint_as_float(f2tf(o1.x)), f11 = __uint_as_float(f2tf(o1.y));
                if (n < 2 * DIM) {
                    // permuted write (Q,K regions): attention cp.asyncs these
                    int j0 = n & 15, j1 = j0 + 1, nb = n & ~15;
                    int np0 = nb | (((j0 & 3) << 2) | (j0 >> 2));
                    int np1 = nb | (((j1 & 3) << 2) | (j1 >> 2));
                    if (row0 < M) {
                        C[(size_t)row0 * Nout + np0] = f00;
                        C[(size_t)row0 * Nout + np1] = f01;
                    }
                    if (row1 < M) {
                        C[(size_t)row1 * Nout + np0] = f10;
                        C[(size_t)row1 * Nout + np1] = f11;
                    }
                } else {
                    if (row0 < M) *(float2*)&C[(size_t)row0 * Nout + n] = make_float2(f00, f01);
                    if (row1 < M) *(float2*)&C[(size_t)row1 * Nout + n] = make_float2(f10, f11);
                }
            } else {
                if (row0 < M) *(float2*)&C[(size_t)row0 * Nout + n] = o0;
                if (row1 < M) *(float2*)&C[(size_t)row1 * Nout + n] = o1;
            }
        }
    }
#undef ISSUE
}

// ---------------------------------------------------------------------------
// Flash attention, tf32 mma. Q/K arrive in GMEM already permuted+tf32 ->
// straight cp.async into smem (stride 80: LDS.128 fragment loads conflict-
// free). V plain row-major (stride 72, scalar fragment loads bank-bijective).
// Softmax scale 1/8 applied at the mask step. Warp-level tile skipping when
// all of the warp's rows mask out the key tile.
// Mask: key allowed iff key < limit(q);
//   limit(q) = 341 (q==0 or q>=85), 5 (q<5), 21 (q<21), 85 (q<85).
// ---------------------------------------------------------------------------
#define AST 80
#define VST 72
__global__ __launch_bounds__(128) void attn_mma(
    const float* __restrict__ qkv, unsigned* __restrict__ op)
{
    extern __shared__ float sm[];
    float* Qs  = sm;                  // [64][80] permuted cols
    float* KPs = sm + 64 * AST;       // [64][80] K tile (permuted), then P
    float* Vs  = sm + 2 * 64 * AST;   // [64][72] row-major [k][d]

    const int qt = blockIdx.x;
    const int bh = blockIdx.y;
    const int b = bh / HEADS, h = bh - b * HEADS;
    const int tid = threadIdx.x;
    const int wid = tid >> 5, lane = tid & 31;
    const int g = lane >> 2, c = lane & 3;
    const int wq = wid * 16;
    const int q0 = qt * 64;
    const float* base = qkv + (size_t)b * SEQ * QKVC + h * HD;

    // Q tile: straight cp.async (already tf32+permuted in GMEM)
    for (int ch = tid; ch < 1024; ch += 128) {
        int row = ch >> 4, cc = (ch & 15) << 2;
        int qg = q0 + row;
        unsigned dst = sptr(&Qs[row * AST + cc]);
        const float* src = base + (size_t)(qg < SEQ ? qg : 0) * QKVC + cc;
        int sz = (qg < SEQ) ? 16 : 0;
        asm volatile("cp.async.cg.shared.global [%0],[%1],16,%2;"
                     :: "r"(dst), "l"(src), "r"(sz));
    }
    asm volatile("cp.async.commit_group;");

    const int row0 = q0 + wq + g;
    const int row1 = row0 + 8;
    const int limit0 = (row0 == 0 || row0 >= 85) ? SEQ : (row0 < 5 ? 5 : (row0 < 21 ? 21 : 85));
    const int limit1 = (row1 == 0 || row1 >= 85) ? SEQ : (row1 < 5 ? 5 : (row1 < 21 ? 21 : 85));

    int lmax = max(limit0, limit1);
#pragma unroll
    for (int sh = 16; sh; sh >>= 1)
        lmax = max(lmax, __shfl_xor_sync(0xffffffffu, lmax, sh));

    float m0 = -1e30f, m1 = -1e30f, l0 = 0.f, l1 = 0.f;
    float O[8][4];
#pragma unroll
    for (int nf = 0; nf < 8; nf++)
#pragma unroll
        for (int t = 0; t < 4; t++) O[nf][t] = 0.f;

    for (int kt = 0; kt < 6; kt++) {
        const int k0 = kt * 64;
        __syncthreads();   // prior tile's P/V reads complete
        for (int ch = tid; ch < 1024; ch += 128) {
            int row = ch >> 4, cc = (ch & 15) << 2;
            int kg = k0 + row;
            int sz = (kg < SEQ) ? 16 : 0;
            const float* srcb = base + (size_t)(kg < SEQ ? kg : 0) * QKVC;
            unsigned kdst = sptr(&KPs[row * AST + cc]);
            asm volatile("cp.async.cg.shared.global [%0],[%1],16,%2;"
                         :: "r"(kdst), "l"(srcb + DIM + cc), "r"(sz));
            unsigned vdst = sptr(&Vs[row * VST + cc]);
            asm volatile("cp.async.cg.shared.global [%0],[%1],16,%2;"
                         :: "r"(vdst), "l"(srcb + 2 * DIM + cc), "r"(sz));
        }
        asm volatile("cp.async.commit_group;");
        asm volatile("cp.async.wait_group 0;");
        __syncthreads();

        const bool active = (k0 < lmax);
        float S[8][4];
        float al0 = 1.f, al1 = 1.f;

        if (active) {
            // S = Q*K^T
#pragma unroll
            for (int nf = 0; nf < 8; nf++)
#pragma unroll
                for (int t = 0; t < 4; t++) S[nf][t] = 0.f;

#pragma unroll
            for (int grp = 0; grp < 4; grp++) {
                const int kb = grp * 16 + 4 * c;
                uint4 qg4 = *(const uint4*)&Qs[(wq + g) * AST + kb];
                uint4 qg8 = *(const uint4*)&Qs[(wq + g + 8) * AST + kb];
                unsigned a0[4] = {qg4.x, qg8.x, qg4.y, qg8.y};
                unsigned a1[4] = {qg4.z, qg8.z, qg4.w, qg8.w};
#pragma unroll
                for (int nf = 0; nf < 8; nf++) {
                    uint4 bv = *(const uint4*)&KPs[(nf * 8 + g) * AST + kb];
                    mma8(S[nf], a0, bv.x, bv.y);
                    mma8(S[nf], a1, bv.z, bv.w);
                }
            }

            // scale + mask + row max
            float mx0 = -1e30f, mx1 = -1e30f;
#pragma unroll
            for (int nf = 0; nf < 8; nf++) {
                int key0 = k0 + nf * 8 + 2 * c;
                int key1 = key0 + 1;
                S[nf][0] = (key0 < limit0) ? S[nf][0] * 0.125f : -1e30f;
                S[nf][1] = (key1 < limit0) ? S[nf][1] * 0.125f : -1e30f;
                S[nf][2] = (key0 < limit1) ? S[nf][2] * 0.125f : -1e30f;
                S[nf][3] = (key1 < limit1) ? S[nf][3] * 0.125f : -1e30f;
                mx0 = fmaxf(mx0, fmaxf(S[nf][0], S[nf][1]));
                mx1 = fmaxf(mx1, fmaxf(S[nf][2], S[nf][3]));
            }
            mx0 = fmaxf(mx0, __shfl_xor_sync(0xffffffffu, mx0, 1));
            mx0 = fmaxf(mx0, __shfl_xor_sync(0xffffffffu, mx0, 2));
            mx1 = fmaxf(mx1, __shfl_xor_sync(0xffffffffu, mx1, 1));
            mx1 = fmaxf(mx1, __shfl_xor_sync(0xffffffffu, mx1, 2));

            float mn0 = fmaxf(m0, mx0), mn1 = fmaxf(m1, mx1);
            al0 = __expf(m0 - mn0); al1 = __expf(m1 - mn1);
            m0 = mn0; m1 = mn1;

            float r0 = 0.f, r1 = 0.f;
#pragma unroll
            for (int nf = 0; nf < 8; nf++) {
                S[nf][0] = __expf(S[nf][0] - mn0);
                S[nf][1] = __expf(S[nf][1] - mn0);
                S[nf][2] = __expf(S[nf][2] - mn1);
                S[nf][3] = __expf(S[nf][3] - mn1);
                r0 += S[nf][0] + S[nf][1];
                r1 += S[nf][2] + S[nf][3];
            }
            r0 += __shfl_xor_sync(0xffffffffu, r0, 1);
            r0 += __shfl_xor_sync(0xffffffffu, r0, 2);
            r1 += __shfl_xor_sync(0xffffffffu, r1, 1);
            r1 += __shfl_xor_sync(0xffffffffu, r1, 2);
            l0 = l0 * al0 + r0;
            l1 = l1 * al1 + r1;
#pragma unroll
            for (int nf = 0; nf < 8; nf++) {
                O[nf][0] *= al0; O[nf][1] *= al0;
                O[nf][2] *= al1; O[nf][3] *= al1;
            }
        }

        __syncthreads();   // ALL warps: K reads done before P overwrites KPs

        if (active) {
            // P -> smem (permuted cols), warp-local rows
#pragma unroll
            for (int nf = 0; nf < 8; nf++) {
                int d0 = nf * 8 + 2 * c;
                int pd = (d0 & ~15) | (((d0 & 3) << 2) | ((d0 >> 2) & 3));
                KPs[(wq + g) * AST + pd]     = S[nf][0];
                KPs[(wq + g) * AST + pd + 4] = S[nf][1];
                KPs[(wq + g + 8) * AST + pd]     = S[nf][2];
                KPs[(wq + g + 8) * AST + pd + 4] = S[nf][3];
            }
            __syncwarp();

            // O += P @ V  (P permuted uint4 + cvt; V raw bits, scalar loads)
#pragma unroll
            for (int grp = 0; grp < 4; grp++) {
                const int kb = grp * 16 + 4 * c;
                const int kr = grp * 16 + c;
                uint4 pg  = *(const uint4*)&KPs[(wq + g) * AST + kb];
                uint4 pg8 = *(const uint4*)&KPs[(wq + g + 8) * AST + kb];
                unsigned a0[4] = {f2tf(__uint_as_float(pg.x)), f2tf(__uint_as_float(pg8.x)),
                                  f2tf(__uint_as_float(pg.y)), f2tf(__uint_as_float(pg8.y))};
                unsigned a1[4] = {f2tf(__uint_as_float(pg.z)), f2tf(__uint_as_float(pg8.z)),
                                  f2tf(__uint_as_float(pg.w)), f2tf(__uint_as_float(pg8.w))};
#pragma unroll
                for (int nf = 0; nf < 8; nf++) {
                    const int dcol = nf * 8 + g;
                    unsigned b0a = __float_as_uint(Vs[(kr)      * VST + dcol]);
                    unsigned b1a = __float_as_uint(Vs[(kr + 4)  * VST + dcol]);
                    unsigned b0b = __float_as_uint(Vs[(kr + 8)  * VST + dcol]);
                    unsigned b1b = __float_as_uint(Vs[(kr + 12) * VST + dcol]);
                    mma8(O[nf], a0, b0a, b1a);
                    mma8(O[nf], a1, b0b, b1b);
                }
            }
        }
    }

    // normalize + store tf32+permuted to g_attn [b, n, h*64 + p(d)]
    float inv0 = 1.f / l0, inv1 = 1.f / l1;
#pragma unroll
    for (int nf = 0; nf < 8; nf++) {
        int d0 = nf * 8 + 2 * c;
        int pd = (d0 & ~15) | (((d0 & 3) << 2) | ((d0 >> 2) & 3));
        int col = h * HD + pd;
        if (row0 < SEQ) {
            unsigned* o = &op[(size_t)(b * SEQ + row0) * DIM + col];
            o[0] = f2tf(O[nf][0] * inv0);
            o[4] = f2tf(O[nf][1] * inv0);
        }
        if (row1 < SEQ) {
            unsigned* o = &op[(size_t)(b * SEQ + row1) * DIM + col];
            o[0] = f2tf(O[nf][2] * inv1);
            o[4] = f2tf(O[nf][3] * inv1);
        }
    }
}

extern "C" void kernel_launch(void* const* d_in, const int* in_sizes, int n_in,
                              void* d_out, int out_size) {
    const float* x      = (const float*)d_in[0];
    const float* qkv_w  = (const float*)d_in[1];
    const float* qkv_b  = (const float*)d_in[2];
    const float* proj_w = (const float*)d_in[3];
    const float* proj_b = (const float*)d_in[4];
    float* out = (float*)d_out;

    unsigned *xp, *wqkvp, *wprojp, *attnp;
    float* qkvp;
    cudaGetSymbolAddress((void**)&xp, g_xp);
    cudaGetSymbolAddress((void**)&wqkvp, g_wqkv);
    cudaGetSymbolAddress((void**)&wprojp, g_wproj);
    cudaGetSymbolAddress((void**)&qkvp, g_qkv);
    cudaGetSymbolAddress((void**)&attnp, g_attn);

    const int gemm_smem = 4 * SSZ * 4;                       // 98304
    const int attn_smem = (2 * 64 * AST + 64 * VST) * 4;     // 59392
    cudaFuncSetAttribute(gemm_tf32p, cudaFuncAttributeMaxDynamicSharedMemorySize, gemm_smem);
    cudaFuncSetAttribute(attn_mma, cudaFuncAttributeMaxDynamicSharedMemorySize, attn_smem);

    prep_tf32<<<(MTOT * DIM + 255) / 256, 256>>>(x, xp, MTOT * DIM, DIM);
    prep_tf32<<<(QKVC * DIM + 255) / 256, 256>>>(qkv_w, wqkvp, QKVC * DIM, DIM);
    prep_tf32<<<(DIM * DIM + 255) / 256, 256>>>(proj_w, wprojp, DIM * DIM, DIM);

    dim3 g1(QKVC / 128, (MTOT + 127) / 128);
    gemm_tf32p<<<g1, 256, gemm_smem>>>(xp, wqkvp, qkv_b, qkvp, MTOT, QKVC, DIM, 1);

    dim3 g2(6, BATCH * HEADS);
    attn_mma<<<g2, 128, attn_smem>>>(qkvp, attnp);

    dim3 g3(DIM / 128, (MTOT + 127) / 128);
    gemm_tf32p<<<g3, 256, gemm_smem>>>(attnp, wprojp, proj_b, out, MTOT, DIM, DIM, 0);
}